// round 10
// baseline (speedup 1.0000x reference)
#include <cuda_runtime.h>
#include <cstdint>

#define NC 32
#define NU 5
#define NV 5
#define NH 64
#define NW 64

#define TILE_H 8
#define TILE_W 32
#define ROWF 40                 // smem row pitch (floats); col j holds w = tw-4+j
#define ROWS 10                 // TILE_H + 2
#define PLF (ROWS * ROWF)       // 400 floats per uv-plane
#define XF (9 * PLF)            // 3600 floats per x stage
#define WF (4 * 27 * 8)         // 864 weights per channel
#define STAGEF (XF + WF)        // 4464
#define SMEM_FLOATS (2 * STAGEF)
#define CHSTRIDE (NU * NV * NH * NW) // 102400

typedef unsigned long long u64;

// Reorganized weights: [c][branch][tap][o], tap = (ka*3+kb)*3+kg
__device__ __align__(128) float g_wr[NC * WF];
__device__ float g_bias[32];
__device__ float g_slope[4];

__global__ void prep_kernel(const float* __restrict__ w0, const float* __restrict__ w1,
                            const float* __restrict__ w2, const float* __restrict__ w3,
                            const float* __restrict__ b0, const float* __restrict__ b1,
                            const float* __restrict__ b2, const float* __restrict__ b3,
                            const float* __restrict__ a0, const float* __restrict__ a1,
                            const float* __restrict__ a2, const float* __restrict__ a3)
{
    int t = blockIdx.x * blockDim.x + threadIdx.x;
    if (t < NC * WF) {
        int o   = t & 7;
        int tap = (t >> 3) % 27;
        int br  = (t / 216) & 3;
        int c   = t / 864;
        const float* w = (br == 0) ? w0 : (br == 1) ? w1 : (br == 2) ? w2 : w3;
        g_wr[t] = w[(o * NC + c) * 27 + tap];
    }
    if (t < 32) {
        const float* b = (t < 8) ? b0 : (t < 16) ? b1 : (t < 24) ? b2 : b3;
        g_bias[t] = b[t & 7];
    }
    if (t < 4) {
        const float* a = (t == 0) ? a0 : (t == 1) ? a1 : (t == 2) ? a2 : a3;
        g_slope[t] = a[0];
    }
}

// ---------- helpers ----------
__device__ __forceinline__ uint32_t smem_u32(const void* p) {
    uint32_t a;
    asm("{ .reg .u64 t; cvta.to.shared.u64 t, %1; cvt.u32.u64 %0, t; }" : "=r"(a) : "l"(p));
    return a;
}
__device__ __forceinline__ void cp16(uint32_t dst, const void* src) {
    asm volatile("cp.async.cg.shared.global [%0], [%1], 16;" :: "r"(dst), "l"(src) : "memory");
}
__device__ __forceinline__ void cp_commit() {
    asm volatile("cp.async.commit_group;" ::: "memory");
}
__device__ __forceinline__ void cp_wait1() {
    asm volatile("cp.async.wait_group 1;" ::: "memory");
}
__device__ __forceinline__ void cp_wait0() {
    asm volatile("cp.async.wait_group 0;" ::: "memory");
}
__device__ __forceinline__ void fma2(u64& acc, u64 a, u64 b) {
    asm("fma.rn.f32x2 %0, %1, %2, %0;" : "+l"(acc) : "l"(a), "l"(b));
}
__device__ __forceinline__ u64 splat2(float v) {
    u64 r;
    asm("mov.b64 %0, {%1, %1};" : "=l"(r) : "f"(v));
    return r;
}
__device__ __forceinline__ float2 unpack2(u64 v) {
    float2 r;
    asm("mov.b64 {%0, %1}, %2;" : "=f"(r.x), "=f"(r.y) : "l"(v));
    return r;
}

// ---------- staging: one channel (x tile + weights) via cp.async ----------
// x: 90 rows (9 uv-planes x 10 h-rows), 10 x 16B chunks per row = 900.
// smem col j holds global w = tw - 4 + j. OOB chunks skipped (smem pre-zeroed;
// OOB pattern channel-invariant). w: 216 x 16B chunks.
__device__ __forceinline__ void stage_channel(const float* __restrict__ xc, int c,
                                              uint32_t sx_u32, uint32_t sw_u32,
                                              int u, int v, int th, int tw, int tid)
{
    #pragma unroll
    for (int i = 0; i < 8; i++) {
        int k = tid + i * 128;
        if (i < 7 || k < 900) {
            int row   = k / 10;
            int chunk = k - row * 10;
            int pidx  = row / 10;
            int r     = row - pidx * 10;
            int pa    = pidx / 3;
            int pb    = pidx - pa * 3;
            int gu = u + pa - 1;
            int gv = v + pb - 1;
            int gh = th + r - 1;
            int gw = tw - 4 + chunk * 4;
            if ((unsigned)gu < NU && (unsigned)gv < NV && (unsigned)gh < NH &&
                (unsigned)gw < NW) {
                const float* src = xc + (((gu * 5 + gv) * NH + gh) << 6) + gw;
                uint32_t dst = sx_u32 + (uint32_t)(row * ROWF + chunk * 4) * 4u;
                cp16(dst, src);
            }
        }
    }
    #pragma unroll
    for (int i = 0; i < 2; i++) {
        int k = tid + i * 128;
        if (k < 216) {
            const float* src = g_wr + c * WF + k * 4;
            cp16(sw_u32 + (uint32_t)k * 16u, src);
        }
    }
}

// ===== per-warp compute: one branch, 8 h-points x 8 oc per thread =====
// acc[p][j]: h point p, oc pair (2j, 2j+1). x col for center w: wl + 4.

// uvx: taps (u, v, h)
__device__ __forceinline__ void comp_uvx(const float* __restrict__ s_x,
                                         const float* __restrict__ s_w,
                                         int wl, u64 (&acc)[8][4])
{
    #pragma unroll
    for (int ab = 0; ab < 9; ab++) {
        const float* col = s_x + ab * PLF + (wl + 4);
        u64 xs[10];
        #pragma unroll
        for (int r = 0; r < 10; r++) xs[r] = splat2(col[r * ROWF]);
        #pragma unroll
        for (int kg = 0; kg < 3; kg++) {
            const float* wp = s_w + (ab * 3 + kg) * 8;
            ulonglong2 w01 = *(const ulonglong2*)wp;
            ulonglong2 w23 = *(const ulonglong2*)(wp + 4);
            #pragma unroll
            for (int p = 0; p < 8; p++) {
                u64 xx = xs[p + kg];
                fma2(acc[p][0], xx, w01.x);
                fma2(acc[p][1], xx, w01.y);
                fma2(acc[p][2], xx, w23.x);
                fma2(acc[p][3], xx, w23.y);
            }
        }
    }
}

// uvy: taps (u, v, w); row p+1, col wl+3+kg
__device__ __forceinline__ void comp_uvy(const float* __restrict__ s_x,
                                         const float* __restrict__ s_w,
                                         int wl, u64 (&acc)[8][4])
{
    #pragma unroll
    for (int ab = 0; ab < 9; ab++) {
        const float* plb = s_x + ab * PLF;
        #pragma unroll
        for (int kg = 0; kg < 3; kg++) {
            const float* col = plb + (wl + 3 + kg);
            const float* wp = s_w + 216 + (ab * 3 + kg) * 8;
            ulonglong2 w01 = *(const ulonglong2*)wp;
            ulonglong2 w23 = *(const ulonglong2*)(wp + 4);
            #pragma unroll
            for (int p = 0; p < 8; p++) {
                u64 xx = splat2(col[(p + 1) * ROWF]);
                fma2(acc[p][0], xx, w01.x);
                fma2(acc[p][1], xx, w01.y);
                fma2(acc[p][2], xx, w23.x);
                fma2(acc[p][3], xx, w23.y);
            }
        }
    }
}

// uxy (planes (ka,1), wbase 432) / vxy (planes (1,ka), wbase 648):
// taps (*, h, w): row p+kb, col wl+3+kg
__device__ __forceinline__ void comp_hw(const float* __restrict__ s_x,
                                        const float* __restrict__ s_w,
                                        int wl, int plane_base, int plane_step,
                                        int wbase, u64 (&acc)[8][4])
{
    #pragma unroll
    for (int ka = 0; ka < 3; ka++) {
        const float* plb = s_x + (plane_base + ka * plane_step) * PLF;
        #pragma unroll
        for (int kg = 0; kg < 3; kg++) {
            const float* col = plb + (wl + 3 + kg);
            u64 xs[10];
            #pragma unroll
            for (int r = 0; r < 10; r++) xs[r] = splat2(col[r * ROWF]);
            #pragma unroll
            for (int kb = 0; kb < 3; kb++) {
                const float* wp = s_w + wbase + ((ka * 3 + kb) * 3 + kg) * 8;
                ulonglong2 w01 = *(const ulonglong2*)wp;
                ulonglong2 w23 = *(const ulonglong2*)(wp + 4);
                #pragma unroll
                for (int p = 0; p < 8; p++) {
                    u64 xx = xs[p + kb];
                    fma2(acc[p][0], xx, w01.x);
                    fma2(acc[p][1], xx, w01.y);
                    fma2(acc[p][2], xx, w23.x);
                    fma2(acc[p][3], xx, w23.y);
                }
            }
        }
    }
}

// ===================== main kernel =====================
__global__ __launch_bounds__(128, 5)
void fe_kernel(const float* __restrict__ x, float* __restrict__ out)
{
    __shared__ __align__(16) float sm[SMEM_FLOATS];
    float* sx0 = sm;
    float* sx1 = sm + STAGEF;
    float* sw0 = sm + XF;
    float* sw1 = sm + STAGEF + XF;
    const uint32_t sx_u[2] = { smem_u32(sx0), smem_u32(sx1) };
    const uint32_t sw_u[2] = { smem_u32(sw0), smem_u32(sw1) };
    const float* sx_p[2] = { sx0, sx1 };
    const float* sw_p[2] = { sw0, sw1 };

    const int tid = threadIdx.x;
    const int br  = tid >> 5;        // warp = branch 0..3
    const int wl  = tid & 31;        // w lane

    const int tile = blockIdx.x;             // 0..15
    const int tw   = (tile & 1) * TILE_W;
    const int th   = (tile >> 1) * TILE_H;   // 0..56
    const int uv   = blockIdx.y;             // 0..24
    const int u    = uv / 5, v = uv % 5;
    const int b    = blockIdx.z;             // 0..7

    // one-time zero (halo + channel-invariant OOB chunks)
    float4* z = (float4*)sm;
    #pragma unroll
    for (int i = tid; i < SMEM_FLOATS / 4; i += 128)
        z[i] = make_float4(0.f, 0.f, 0.f, 0.f);
    __syncthreads();

    const float* xb = x + (size_t)b * (NC * CHSTRIDE);

    stage_channel(xb, 0, sx_u[0], sw_u[0], u, v, th, tw, tid);
    cp_commit();

    u64 acc[8][4];
    #pragma unroll
    for (int p = 0; p < 8; p++)
        #pragma unroll
        for (int j = 0; j < 4; j++) acc[p][j] = 0ull;

    #pragma unroll 1
    for (int c = 0; c < NC; c++) {
        const int s = c & 1;
        if (c < NC - 1) {
            stage_channel(xb + (size_t)(c + 1) * CHSTRIDE, c + 1,
                          sx_u[s ^ 1], sw_u[s ^ 1], u, v, th, tw, tid);
            cp_commit();
            cp_wait1();
        } else {
            cp_wait0();
        }
        __syncthreads();

        if (br == 0)      comp_uvx(sx_p[s], sw_p[s], wl, acc);
        else if (br == 1) comp_uvy(sx_p[s], sw_p[s], wl, acc);
        else if (br == 2) comp_hw(sx_p[s], sw_p[s], wl, 1, 3, 432, acc); // uxy
        else              comp_hw(sx_p[s], sw_p[s], wl, 3, 1, 648, acc); // vxy
        __syncthreads();
    }

    // ---- epilogue: bias + PReLU + store ----
    const float slope = g_slope[br];
    const int ocb = br * 8;
    const size_t base0 = (size_t)b * 32 * CHSTRIDE + (size_t)ocb * CHSTRIDE +
                         (size_t)uv * (NH * NW) + (size_t)th * NW + (size_t)(tw + wl);
    #pragma unroll
    for (int j = 0; j < 4; j++) {
        const float b0 = g_bias[ocb + j * 2];
        const float b1 = g_bias[ocb + j * 2 + 1];
        const size_t cb0 = base0 + (size_t)(j * 2) * CHSTRIDE;
        const size_t cb1 = base0 + (size_t)(j * 2 + 1) * CHSTRIDE;
        #pragma unroll
        for (int p = 0; p < 8; p++) {
            float2 y = unpack2(acc[p][j]);
            float y0 = y.x + b0;
            float y1 = y.y + b1;
            y0 = (y0 >= 0.f) ? y0 : slope * y0;
            y1 = (y1 >= 0.f) ? y1 : slope * y1;
            out[cb0 + (size_t)p * NW] = y0;
            out[cb1 + (size_t)p * NW] = y1;
        }
    }
}

extern "C" void kernel_launch(void* const* d_in, const int* in_sizes, int n_in,
                              void* d_out, int out_size)
{
    const float* x = (const float*)d_in[0];

    prep_kernel<<<(NC * WF + 255) / 256, 256>>>(
        (const float*)d_in[1], (const float*)d_in[4],
        (const float*)d_in[7], (const float*)d_in[10],
        (const float*)d_in[2], (const float*)d_in[5],
        (const float*)d_in[8], (const float*)d_in[11],
        (const float*)d_in[3], (const float*)d_in[6],
        (const float*)d_in[9], (const float*)d_in[12]);

    dim3 grid(16, 25, 8);   // (hw tiles: 2w x 8h, uv, batch)
    fe_kernel<<<grid, 128>>>(x, (float*)d_out);
}

// round 11
// speedup vs baseline: 1.6808x; 1.6808x over previous
#include <cuda_runtime.h>
#include <cstdint>

#define NC 32
#define NU 5
#define NV 5
#define NH 64
#define NW 64

#define TILE_H 4
#define TILE_W 32
#define CHSTRIDE (NU * NV * NH * NW)   // 102400

typedef unsigned long long u64;

// x-buffer float sizes per branch stage: uvx 9pl*6r*40, uvy 9pl*4r*40, uxy/vxy 3pl*6r*40
#define XPRE0 0
#define XPRE1 2160
#define XPRE2 3600
#define XPRE3 4320
#define XTOT  5040
#define WPER  216                       // floats per branch per channel
#define STAGEF (XTOT + 4 * WPER)        // 5904 floats per stage
#define SMEM_FLOATS (2 * STAGEF)        // 11808 (47232 B)

// Reorganized weights: [c][branch][tap][o], tap = (ka*3+kb)*3+kg
__device__ __align__(128) float g_wr[NC * 864];
__device__ float g_bias[32];
__device__ float g_slope[4];

__global__ void prep_kernel(const float* __restrict__ w0, const float* __restrict__ w1,
                            const float* __restrict__ w2, const float* __restrict__ w3,
                            const float* __restrict__ b0, const float* __restrict__ b1,
                            const float* __restrict__ b2, const float* __restrict__ b3,
                            const float* __restrict__ a0, const float* __restrict__ a1,
                            const float* __restrict__ a2, const float* __restrict__ a3)
{
    int t = blockIdx.x * blockDim.x + threadIdx.x;
    if (t < NC * 864) {
        int o   = t & 7;
        int tap = (t >> 3) % 27;
        int br  = (t / 216) & 3;
        int c   = t / 864;
        const float* w = (br == 0) ? w0 : (br == 1) ? w1 : (br == 2) ? w2 : w3;
        g_wr[t] = w[(o * NC + c) * 27 + tap];
    }
    if (t < 32) {
        const float* b = (t < 8) ? b0 : (t < 16) ? b1 : (t < 24) ? b2 : b3;
        g_bias[t] = b[t & 7];
    }
    if (t < 4) {
        const float* a = (t == 0) ? a0 : (t == 1) ? a1 : (t == 2) ? a2 : a3;
        g_slope[t] = a[0];
    }
}

// ---------- helpers ----------
__device__ __forceinline__ uint32_t smem_u32(const void* p) {
    uint32_t a;
    asm("{ .reg .u64 t; cvta.to.shared.u64 t, %1; cvt.u32.u64 %0, t; }" : "=r"(a) : "l"(p));
    return a;
}
__device__ __forceinline__ void cp16(uint32_t dst, const void* src) {
    asm volatile("cp.async.cg.shared.global [%0], [%1], 16;" :: "r"(dst), "l"(src) : "memory");
}
__device__ __forceinline__ void cp_commit() {
    asm volatile("cp.async.commit_group;" ::: "memory");
}
__device__ __forceinline__ void cp_wait1() {
    asm volatile("cp.async.wait_group 1;" ::: "memory");
}
__device__ __forceinline__ void cp_wait0() {
    asm volatile("cp.async.wait_group 0;" ::: "memory");
}
__device__ __forceinline__ void fma2(u64& acc, u64 a, u64 b) {
    asm("fma.rn.f32x2 %0, %1, %2, %0;" : "+l"(acc) : "l"(a), "l"(b));
}
__device__ __forceinline__ u64 splat2(float v) {
    u64 r;
    asm("mov.b64 %0, {%1, %1};" : "=l"(r) : "f"(v));
    return r;
}
__device__ __forceinline__ float2 unpack2(u64 v) {
    float2 r;
    asm("mov.b64 {%0, %1}, %2;" : "=f"(r.x), "=f"(r.y) : "l"(v));
    return r;
}

// ===== per-warp compute: one branch, 4 h-points x 8 oc per thread =====
// acc[p][j]: h point p, oc pair (2j, 2j+1). All buffers warp-private.

// uvx: 9 planes (stride 240), 6 rows (stride 40); center col wl+4.
__device__ __forceinline__ void comp_uvx(const float* __restrict__ s_x,
                                         const float* __restrict__ s_w,
                                         int wl, u64 (&acc)[4][4])
{
    #pragma unroll
    for (int ab = 0; ab < 9; ab++) {
        const float* col = s_x + ab * 240 + (wl + 4);
        u64 xs[6];
        #pragma unroll
        for (int r = 0; r < 6; r++) xs[r] = splat2(col[r * 40]);
        #pragma unroll
        for (int kg = 0; kg < 3; kg++) {
            const float* wp = s_w + (ab * 3 + kg) * 8;
            ulonglong2 w01 = *(const ulonglong2*)wp;
            ulonglong2 w23 = *(const ulonglong2*)(wp + 4);
            #pragma unroll
            for (int p = 0; p < 4; p++) {
                u64 xx = xs[p + kg];
                fma2(acc[p][0], xx, w01.x);
                fma2(acc[p][1], xx, w01.y);
                fma2(acc[p][2], xx, w23.x);
                fma2(acc[p][3], xx, w23.y);
            }
        }
    }
}

// uvy: 9 planes (stride 160), 4 rows (stride 40); col wl+3+kg, row p.
__device__ __forceinline__ void comp_uvy(const float* __restrict__ s_x,
                                         const float* __restrict__ s_w,
                                         int wl, u64 (&acc)[4][4])
{
    #pragma unroll
    for (int ab = 0; ab < 9; ab++) {
        const float* plb = s_x + ab * 160;
        #pragma unroll
        for (int kg = 0; kg < 3; kg++) {
            const float* col = plb + (wl + 3 + kg);
            const float* wp = s_w + (ab * 3 + kg) * 8;
            ulonglong2 w01 = *(const ulonglong2*)wp;
            ulonglong2 w23 = *(const ulonglong2*)(wp + 4);
            #pragma unroll
            for (int p = 0; p < 4; p++) {
                u64 xx = splat2(col[p * 40]);
                fma2(acc[p][0], xx, w01.x);
                fma2(acc[p][1], xx, w01.y);
                fma2(acc[p][2], xx, w23.x);
                fma2(acc[p][3], xx, w23.y);
            }
        }
    }
}

// uxy / vxy: 3 planes (stride 240), 6 rows; row p+kb, col wl+3+kg.
__device__ __forceinline__ void comp_hw(const float* __restrict__ s_x,
                                        const float* __restrict__ s_w,
                                        int wl, u64 (&acc)[4][4])
{
    #pragma unroll
    for (int ka = 0; ka < 3; ka++) {
        const float* plb = s_x + ka * 240;
        #pragma unroll
        for (int kg = 0; kg < 3; kg++) {
            const float* col = plb + (wl + 3 + kg);
            u64 xs[6];
            #pragma unroll
            for (int r = 0; r < 6; r++) xs[r] = splat2(col[r * 40]);
            #pragma unroll
            for (int kb = 0; kb < 3; kb++) {
                const float* wp = s_w + ((ka * 3 + kb) * 3 + kg) * 8;
                ulonglong2 w01 = *(const ulonglong2*)wp;
                ulonglong2 w23 = *(const ulonglong2*)(wp + 4);
                #pragma unroll
                for (int p = 0; p < 4; p++) {
                    u64 xx = xs[p + kb];
                    fma2(acc[p][0], xx, w01.x);
                    fma2(acc[p][1], xx, w01.y);
                    fma2(acc[p][2], xx, w23.x);
                    fma2(acc[p][3], xx, w23.y);
                }
            }
        }
    }
}

// ===================== main kernel =====================
__global__ __launch_bounds__(128, 4)
void fe_kernel(const float* __restrict__ x, float* __restrict__ out)
{
    __shared__ __align__(16) float sm[SMEM_FLOATS];

    const int tid = threadIdx.x;
    const int br  = tid >> 5;        // warp = branch 0..3
    const int wl  = tid & 31;        // w lane

    const int tile = blockIdx.x;             // 0..31
    const int tw   = (tile & 1) * TILE_W;
    const int th   = (tile >> 1) * TILE_H;   // 0..60
    const int uv   = blockIdx.y;             // 0..24
    const int u    = uv / 5, v = uv % 5;
    const int b    = blockIdx.z;             // 0..7

    // one-time zero (covers halo + OOB chunks; pattern channel-invariant)
    float4* z = (float4*)sm;
    #pragma unroll
    for (int i = tid; i < SMEM_FLOATS / 4; i += 128)
        z[i] = make_float4(0.f, 0.f, 0.f, 0.f);
    __syncthreads();

    // per-branch buffer bases
    const int xpre = (br == 0) ? XPRE0 : (br == 1) ? XPRE1 : (br == 2) ? XPRE2 : XPRE3;
    const float* sx_p[2] = { sm + xpre, sm + STAGEF + xpre };
    const float* sw_p[2] = { sm + XTOT + br * WPER, sm + STAGEF + XTOT + br * WPER };
    uint32_t xdst[2], wdst[2];
    xdst[0] = smem_u32(sx_p[0]) + wl * 16;
    xdst[1] = smem_u32(sx_p[1]) + wl * 16;
    wdst[0] = smem_u32(sw_p[0]) + wl * 16;
    wdst[1] = smem_u32(sw_p[1]) + wl * 16;

    // ---- channel-invariant per-lane src offsets (bytes within a channel) ----
    int srcoff[17];
    #pragma unroll
    for (int i = 0; i < 17; i++) srcoff[i] = -1;
    if (br == 0) {              // uvx: 540 chunks, 9 planes x 6 rows x 10 chunks
        #pragma unroll
        for (int i = 0; i < 17; i++) {
            int k = wl + 32 * i;
            if (k < 540) {
                int row = k / 10, ch = k - row * 10;
                int ab = row / 6, r = row - ab * 6;
                int pa = ab / 3, pb = ab - pa * 3;
                int gu = u + pa - 1, gv = v + pb - 1;
                int gh = th + r - 1, gw = tw - 4 + ch * 4;
                if ((unsigned)gu < 5u && (unsigned)gv < 5u &&
                    (unsigned)gh < 64u && (unsigned)gw < 64u)
                    srcoff[i] = (((gu * 5 + gv) * 64 + gh) * 64 + gw) * 4;
            }
        }
    } else if (br == 1) {       // uvy: 360 chunks, 9 planes x 4 rows x 10
        #pragma unroll
        for (int i = 0; i < 12; i++) {
            int k = wl + 32 * i;
            if (k < 360) {
                int row = k / 10, ch = k - row * 10;
                int ab = row / 4, r = row - ab * 4;
                int pa = ab / 3, pb = ab - pa * 3;
                int gu = u + pa - 1, gv = v + pb - 1;
                int gh = th + r, gw = tw - 4 + ch * 4;
                if ((unsigned)gu < 5u && (unsigned)gv < 5u && (unsigned)gw < 64u)
                    srcoff[i] = (((gu * 5 + gv) * 64 + gh) * 64 + gw) * 4;
            }
        }
    } else {                    // uxy / vxy: 180 chunks, 3 planes x 6 rows x 10
        #pragma unroll
        for (int i = 0; i < 6; i++) {
            int k = wl + 32 * i;
            if (k < 180) {
                int row = k / 10, ch = k - row * 10;
                int pk = row / 6, r = row - pk * 6;
                int gu = (br == 2) ? (u + pk - 1) : u;
                int gv = (br == 2) ? v : (v + pk - 1);
                int gh = th + r - 1, gw = tw - 4 + ch * 4;
                if ((unsigned)gu < 5u && (unsigned)gv < 5u &&
                    (unsigned)gh < 64u && (unsigned)gw < 64u)
                    srcoff[i] = (((gu * 5 + gv) * 64 + gh) * 64 + gw) * 4;
            }
        }
    }

    const char* xb = (const char*)(x + (size_t)b * NC * CHSTRIDE);
    const char* wbch = (const char*)(g_wr + br * WPER);
    const bool w2nd = (wl < 22);   // weight chunks: 54 per channel

    // ---- stage channel 0 into buffer 0 ----
    {
        const char* xc = xb;
        #pragma unroll
        for (int i = 0; i < 17; i++)
            if (srcoff[i] >= 0) cp16(xdst[0] + i * 512, xc + srcoff[i]);
        cp16(wdst[0], wbch + wl * 16);
        if (w2nd) cp16(wdst[0] + 512, wbch + 512 + wl * 16);
    }
    cp_commit();

    u64 acc[4][4];
    #pragma unroll
    for (int p = 0; p < 4; p++)
        #pragma unroll
        for (int j = 0; j < 4; j++) acc[p][j] = 0ull;

    #pragma unroll 1
    for (int c = 0; c < NC; c++) {
        const int s = c & 1;
        if (c < NC - 1) {
            __syncwarp();   // all lanes done computing c-1 before overwriting s^1
            const char* xc = xb + (size_t)(c + 1) * (CHSTRIDE * 4);
            const char* wc = wbch + (size_t)(c + 1) * (864 * 4);
            #pragma unroll
            for (int i = 0; i < 17; i++)
                if (srcoff[i] >= 0) cp16(xdst[s ^ 1] + i * 512, xc + srcoff[i]);
            cp16(wdst[s ^ 1], wc + wl * 16);
            if (w2nd) cp16(wdst[s ^ 1] + 512, wc + 512 + wl * 16);
            cp_commit();
            cp_wait1();
        } else {
            cp_wait0();
        }
        __syncwarp();

        if (br == 0)      comp_uvx(sx_p[s], sw_p[s], wl, acc);
        else if (br == 1) comp_uvy(sx_p[s], sw_p[s], wl, acc);
        else              comp_hw(sx_p[s], sw_p[s], wl, acc);
    }

    // ---- epilogue: bias + PReLU + store (warp-private, no sync) ----
    const float slope = g_slope[br];
    const int ocb = br * 8;
    const size_t base0 = (size_t)b * 32 * CHSTRIDE + (size_t)ocb * CHSTRIDE +
                         (size_t)uv * (NH * NW) + (size_t)th * NW + (size_t)(tw + wl);
    #pragma unroll
    for (int j = 0; j < 4; j++) {
        const float b0 = g_bias[ocb + j * 2];
        const float b1 = g_bias[ocb + j * 2 + 1];
        const size_t cb0 = base0 + (size_t)(j * 2) * CHSTRIDE;
        const size_t cb1 = base0 + (size_t)(j * 2 + 1) * CHSTRIDE;
        #pragma unroll
        for (int p = 0; p < 4; p++) {
            float2 y = unpack2(acc[p][j]);
            float y0 = y.x + b0;
            float y1 = y.y + b1;
            y0 = (y0 >= 0.f) ? y0 : slope * y0;
            y1 = (y1 >= 0.f) ? y1 : slope * y1;
            out[cb0 + (size_t)p * NW] = y0;
            out[cb1 + (size_t)p * NW] = y1;
        }
    }
}

extern "C" void kernel_launch(void* const* d_in, const int* in_sizes, int n_in,
                              void* d_out, int out_size)
{
    const float* x = (const float*)d_in[0];

    prep_kernel<<<(NC * 864 + 255) / 256, 256>>>(
        (const float*)d_in[1], (const float*)d_in[4],
        (const float*)d_in[7], (const float*)d_in[10],
        (const float*)d_in[2], (const float*)d_in[5],
        (const float*)d_in[8], (const float*)d_in[11],
        (const float*)d_in[3], (const float*)d_in[6],
        (const float*)d_in[9], (const float*)d_in[12]);

    dim3 grid(32, 25, 8);   // (hw tiles: 2w x 16h, uv, batch)
    fe_kernel<<<grid, 128>>>(x, (float*)d_out);
}